// round 17
// baseline (speedup 1.0000x reference)
#include <cuda_runtime.h>

#define L 64
#define C 7
#define NSTEPS 126   // (L-1)*K, K=2, h=0.5
#define NBPAIR 5     // batches per warp-pair
#define NCTA 410     // 410 CTAs x 2 pairs x 5 = 4100 >= 4096

typedef unsigned long long ull;

__device__ __forceinline__ ull ffma2(ull a, ull b, ull c) {
    ull d;
    asm("fma.rn.f32x2 %0, %1, %2, %3;" : "=l"(d) : "l"(a), "l"(b), "l"(c));
    return d;
}
__device__ __forceinline__ ull pk2(float x, float y) {
    ull r;
    asm("mov.b64 %0, {%1, %2};" : "=l"(r) : "f"(x), "f"(y));
    return r;
}
__device__ __forceinline__ void upk2(ull v, float &x, float &y) {
    asm("mov.b64 {%0, %1}, %2;" : "=f"(x), "=f"(y) : "l"(v));
}
__device__ __forceinline__ float sp_(float x) {
    return fmaxf(x, 0.f) + __logf(1.f + __expf(-fabsf(x)));
}
__device__ __forceinline__ float tanh_(float x) {
    float y;
    asm("tanh.approx.f32 %0, %1;" : "=f"(y) : "f"(x));
    return y;
}

#define BAR_ARRIVE(id) asm volatile("bar.arrive %0, 64;" :: "r"(id) : "memory")
#define BAR_SYNCN(id)  asm volatile("bar.sync %0, 64;"   :: "r"(id) : "memory")

// mm1 for NB batches starting at row sZb (stride 32), h1 -> sH1b
template<int NB>
__device__ __forceinline__ void mm1_run(const float* sZb, const ull* rw1, float rbf1,
                                        float* sH1b, int lane) {
    ull a1[NB];
#pragma unroll
    for (int k = 0; k < NB; k++) a1[k] = 0ull;
#pragma unroll
    for (int q = 0; q < 8; q++) {
#pragma unroll
        for (int k = 0; k < NB; k++) {
            ulonglong2 zq = *reinterpret_cast<const ulonglong2*>(sZb + k * 32 + 4 * q);
            a1[k] = ffma2(zq.x, rw1[2 * q], a1[k]);
            a1[k] = ffma2(zq.y, rw1[2 * q + 1], a1[k]);
        }
    }
#pragma unroll
    for (int k = 0; k < NB; k++) {
        float u, v; upk2(a1[k], u, v);
        sH1b[k * 32 + lane] = sp_(u + v + rbf1);
    }
}

// mm2 + tanh + einsum partial for TWO batches (NCH own channels)
template<int NCH>
__device__ __forceinline__ void mm2_two(const float* h0, const float* h1,
                                        const float* d0, const float* d1,
                                        const ull (*wreg)[16], const float* b2,
                                        float& r0, float& r1) {
    ull a0[NCH], a1[NCH];
#pragma unroll
    for (int c = 0; c < NCH; c++) { a0[c] = 0ull; a1[c] = 0ull; }
#pragma unroll
    for (int q = 0; q < 8; q++) {
        ulonglong2 hq0 = *reinterpret_cast<const ulonglong2*>(h0 + 4 * q);
        ulonglong2 hq1 = *reinterpret_cast<const ulonglong2*>(h1 + 4 * q);
#pragma unroll
        for (int c = 0; c < NCH; c++) {
            a0[c] = ffma2(hq0.x, wreg[c][2 * q], a0[c]);
            a1[c] = ffma2(hq1.x, wreg[c][2 * q], a1[c]);
            a0[c] = ffma2(hq0.y, wreg[c][2 * q + 1], a0[c]);
            a1[c] = ffma2(hq1.y, wreg[c][2 * q + 1], a1[c]);
        }
    }
    float g0[NCH], g1[NCH];
#pragma unroll
    for (int c = 0; c < NCH; c++) {
        float u, v;
        upk2(a0[c], u, v); g0[c] = tanh_(u + v + b2[c]);
        upk2(a1[c], u, v); g1[c] = tanh_(u + v + b2[c]);
    }
    ull e0 = ffma2(pk2(g0[0], g0[1]), *reinterpret_cast<const ull*>(d0), 0ull);
    ull e1 = ffma2(pk2(g1[0], g1[1]), *reinterpret_cast<const ull*>(d1), 0ull);
    if (NCH == 4) {
        e0 = ffma2(pk2(g0[2], g0[3]), *reinterpret_cast<const ull*>(d0 + 2), e0);
        e1 = ffma2(pk2(g1[2], g1[3]), *reinterpret_cast<const ull*>(d1 + 2), e1);
    }
    float a, b;
    upk2(e0, a, b); r0 = a + b;
    upk2(e1, a, b); r1 = a + b;
    if (NCH == 3) {
        r0 = fmaf(g0[2], d0[2], r0);
        r1 = fmaf(g1[2], d1[2], r1);
    }
}

// single-batch variant
template<int NCH>
__device__ __forceinline__ float mm2_one(const float* h0, const float* d0,
                                         const ull (*wreg)[16], const float* b2) {
    ull a0[NCH];
#pragma unroll
    for (int c = 0; c < NCH; c++) a0[c] = 0ull;
#pragma unroll
    for (int q = 0; q < 8; q++) {
        ulonglong2 hq0 = *reinterpret_cast<const ulonglong2*>(h0 + 4 * q);
#pragma unroll
        for (int c = 0; c < NCH; c++) {
            a0[c] = ffma2(hq0.x, wreg[c][2 * q], a0[c]);
            a0[c] = ffma2(hq0.y, wreg[c][2 * q + 1], a0[c]);
        }
    }
    float g0[NCH];
#pragma unroll
    for (int c = 0; c < NCH; c++) {
        float u, v; upk2(a0[c], u, v);
        g0[c] = tanh_(u + v + b2[c]);
    }
    ull e0 = ffma2(pk2(g0[0], g0[1]), *reinterpret_cast<const ull*>(d0), 0ull);
    if (NCH == 4) e0 = ffma2(pk2(g0[2], g0[3]), *reinterpret_cast<const ull*>(d0 + 2), e0);
    float a, b; upk2(e0, a, b);
    float r = a + b;
    if (NCH == 3) r = fmaf(g0[2], d0[2], r);
    return r;
}

__global__ __launch_bounds__(128, 3)
void cde_kernel(const float* __restrict__ X,      // (4096,64,7)
                const float* __restrict__ Winit,  // (32,7)
                const float* __restrict__ binit,  // (32)
                const float* __restrict__ Wf1,    // (32,32)
                const float* __restrict__ bf1,    // (32)
                const float* __restrict__ Wf2,    // (224,32)
                const float* __restrict__ bf2,    // (224)
                const float* __restrict__ Wo1,    // (16,32)
                const float* __restrict__ bo1,    // (16)
                const float* __restrict__ Wo2,    // (3,16)
                const float* __restrict__ bo2,    // (3)
                float* __restrict__ out)          // (4096,3)
{
    // 4 warps = 2 pairs; pair serves 5 batches.
    // Warp A (isB=0): PURE channel engine, ch {0..3} for all 5 batches. No state.
    // Warp B (isB=1): mm1 all 5, ch {4,5,6}, RK4 state + combine + output.
    __shared__ __align__(16) float sZ[2][NBPAIR][32];      // B-written zs
    __shared__ __align__(16) float sH1[2][NBPAIR][32];     // B-written h1
    __shared__ __align__(16) float sDX[2][3][NBPAIR][8];   // A rows 0-3, B row 4
    __shared__ __align__(16) float sPartX[2][NBPAIR][32];  // A-written ch0-3 partials

    const int tid  = threadIdx.x;
    const int w    = tid >> 5;
    const int lane = tid & 31;          // = h
    const int pair = w >> 1;
    const int isB  = w & 1;
    const int gpair = blockIdx.x * 2 + pair;
    const int pairbase = gpair * NBPAIR;

    // barriers (count 64): b0=dX ready (A->B, per step)
    // b1 = h1 rows{0,1,2} (B->A), b2 = h1 rows{3,4} (B->A)
    // b4 = partials rows{0,1,2} (A->B), b5 = partials rows{3,4} (A->B)
    const int b0 = pair * 5 + 1, b1 = pair * 5 + 2, b2i = pair * 5 + 3;
    const int b4 = pair * 5 + 4, b5 = pair * 5 + 5;

    // ---- role-specific weights ----
    ull wreg[4][16];
    float bb2[4];
    ull rw1[16];
    float rbf1 = 0.f;
    const int nch = isB ? 3 : 4;
    const int c0  = isB ? 4 : 0;
#pragma unroll
    for (int cp = 0; cp < 4; cp++) {
        if (cp < nch) {
            int cg = c0 + cp;
            const float2* wp = reinterpret_cast<const float2*>(Wf2 + (lane * C + cg) * 32);
#pragma unroll
            for (int jp = 0; jp < 16; jp++) { float2 v = __ldg(wp + jp); wreg[cp][jp] = pk2(v.x, v.y); }
            bb2[cp] = __ldg(bf2 + lane * C + cg);
        } else {
#pragma unroll
            for (int jp = 0; jp < 16; jp++) wreg[cp][jp] = 0ull;
            bb2[cp] = 0.f;
        }
    }
    if (isB) {
        const float2* p1 = reinterpret_cast<const float2*>(Wf1 + lane * 32);
#pragma unroll
        for (int jp = 0; jp < 16; jp++) { float2 v = __ldg(p1 + jp); rw1[jp] = pk2(v.x, v.y); }
        rbf1 = __ldg(bf1 + lane);
    } else {
#pragma unroll
        for (int jp = 0; jp < 16; jp++) rw1[jp] = 0ull;
    }

    // spline mapping: A -> rows 0..3 (db=lane>>3, dc=lane&7); B -> row 4 (lane<C)
    const int db = isB ? 4 : (lane >> 3);
    const int dc = isB ? lane : (lane & 7);
    const bool spl = isB ? (lane < C) : (dc < C);
    const int sbatch = min(pairbase + db, 4095);
    const float* xrow = X + (size_t)sbatch * (L * C) + (spl ? dc : 0);

    // B: z0 for all 5 batches
    float z[NBPAIR], ksum[NBPAIR];
#pragma unroll
    for (int k = 0; k < NBPAIR; k++) { z[k] = 0.f; ksum[k] = 0.f; }
    if (isB) {
#pragma unroll
        for (int k = 0; k < NBPAIR; k++) {
            int gb = min(pairbase + k, 4095);
            float acc = __ldg(binit + lane);
            const float* xp = X + (size_t)gb * (L * C);
#pragma unroll
            for (int c = 0; c < C; c++) acc = fmaf(__ldg(xp + c), __ldg(Winit + lane * C + c), acc);
            z[k] = acc;
            sZ[pair][k][lane] = acc;
        }
    }

    // initial dX(t=0) -> slot 0 (= diff)
    if (spl) {
        float v = __ldg(xrow + C) - __ldg(xrow);
        sDX[pair][0][db][dc] = v;
    }
    __syncthreads();

    // stencil carry (updated on even i)
    float st_diff = 0.f, st_m0 = 0.f, st_dm = 0.f;

#pragma unroll 1
    for (int i = 0; i < NSTEPS; i++) {
        // ---- spline writes: slots 2 (mid) and (i+1)&1 (end) ----
        {
            if (!(i & 1)) {
                const int m = i >> 1;
                const float* p = xrow + m * C;
                float xm1 = 0.f, x0 = 0.f, x1 = 0.f;
                if (spl) {
                    x0 = __ldg(p);
                    x1 = __ldg(p + C);
                    if (m > 0) xm1 = __ldg(p - C);
                }
                st_diff = x1 - x0;
                st_m0 = (m > 0) ? (x0 - xm1) : st_diff;
                st_dm = st_diff - st_m0;
            }
            float fac = (i & 1) ? 1.3125f : 0.8125f;
            float vb = fmaf(st_dm, fac, st_m0);
            float vc = (i & 1) ? st_diff : fmaf(st_dm, 1.25f, st_m0);
            if (spl) {
                sDX[pair][2][db][dc] = vb;
                sDX[pair][(i + 1) & 1][db][dc] = vc;
            }
        }
        if (!isB) BAR_ARRIVE(b0);   // A's dX rows 0-3 published (once per step)
        const int slotA = i & 1, slotC = (i + 1) & 1;

#pragma unroll 1
        for (int s = 0; s < 4; s++) {
            const int slot = (s == 0) ? slotA : ((s == 3) ? slotC : 2);
            const float* dxs = &sDX[pair][slot][0][0];   // rows of 8
            float* sPx = &sPartX[pair][0][0];
            const float* h1t = &sH1[pair][0][0];
            const float wk = (s == 1 || s == 2) ? 2.f : 1.f;
            const float an = (s < 2) ? 0.25f : 0.5f;

            if (!isB) {
                // ---- A: pure 4-channel engine over B's h1 chunks ----
                BAR_SYNCN(b1);                // h1 rows {0,1,2}
                {
                    float r0, r1;
                    mm2_two<4>(h1t, h1t + 32, dxs, dxs + 8, wreg, bb2, r0, r1);
                    sPx[lane] = r0; sPx[32 + lane] = r1;
                    sPx[64 + lane] = mm2_one<4>(h1t + 64, dxs + 16, wreg, bb2);
                }
                BAR_ARRIVE(b4);
                BAR_SYNCN(b2i);               // h1 rows {3,4}
                {
                    float r0, r1;
                    mm2_two<4>(h1t + 96, h1t + 128, dxs + 24, dxs + 32, wreg, bb2, r0, r1);
                    sPx[96 + lane] = r0; sPx[128 + lane] = r1;
                }
                BAR_ARRIVE(b5);
            } else {
                // ---- B: mm1 chunks -> own mm2 (ch4-6) -> split combine ----
                __syncwarp();
                mm1_run<3>(&sZ[pair][0][0], rw1, rbf1, &sH1[pair][0][0], lane);
                BAR_ARRIVE(b1);
                mm1_run<2>(&sZ[pair][3][0], rw1, rbf1, &sH1[pair][3][0], lane);
                BAR_ARRIVE(b2i);
                if (s == 0) BAR_SYNCN(b0);    // this step's dX rows 0-3 visible
                float ownp[NBPAIR];
                {
                    mm2_two<3>(h1t, h1t + 32, dxs + 4, dxs + 8 + 4, wreg, bb2, ownp[0], ownp[1]);
                    mm2_two<3>(h1t + 64, h1t + 96, dxs + 16 + 4, dxs + 24 + 4, wreg, bb2, ownp[2], ownp[3]);
                    ownp[4] = mm2_one<3>(h1t + 128, dxs + 32 + 4, wreg, bb2);
                }
                BAR_SYNCN(b4);                // A partials rows {0,1,2}
#pragma unroll
                for (int k = 0; k < 3; k++) {
                    float kk = ownp[k] + sPx[k * 32 + lane];
                    ksum[k] = fmaf(wk, kk, ksum[k]);
                    float zsv;
                    if (s < 3) {
                        zsv = fmaf(an, kk, z[k]);
                    } else {
                        z[k] = fmaf(ksum[k], (1.f / 12.f), z[k]);  // h/6
                        ksum[k] = 0.f;
                        zsv = z[k];
                    }
                    sZ[pair][k][lane] = zsv;
                }
                BAR_SYNCN(b5);                // A partials rows {3,4}
#pragma unroll
                for (int k = 3; k < NBPAIR; k++) {
                    float kk = ownp[k] + sPx[k * 32 + lane];
                    ksum[k] = fmaf(wk, kk, ksum[k]);
                    float zsv;
                    if (s < 3) {
                        zsv = fmaf(an, kk, z[k]);
                    } else {
                        z[k] = fmaf(ksum[k], (1.f / 12.f), z[k]);
                        ksum[k] = 0.f;
                        zsv = z[k];
                    }
                    sZ[pair][k][lane] = zsv;
                }
            }
        }
    }

    // ---- output head: B only (A is done; all barrier pairs matched) ----
    if (isB) {
        __syncwarp();
        float* so = &sPartX[pair][0][0];   // scratch [5][32]; A no longer writes
        if (lane < 16) {
#pragma unroll
            for (int k = 0; k < NBPAIR; k++) {
                float acc = __ldg(bo1 + lane);
#pragma unroll
                for (int hh = 0; hh < 32; hh++)
                    acc = fmaf(sZ[pair][k][hh], __ldg(Wo1 + lane * 32 + hh), acc);
                so[k * 32 + lane] = sp_(acc);
            }
        }
        __syncwarp();
        if (lane < 3 * NBPAIR) {
            int k = lane / 3;
            int jo = lane - 3 * k;
            int gb = pairbase + k;
            if (gb < 4096) {
                float acc = __ldg(bo2 + jo);
#pragma unroll
                for (int i2 = 0; i2 < 16; i2++)
                    acc = fmaf(so[k * 32 + i2], __ldg(Wo2 + jo * 16 + i2), acc);
                out[(size_t)gb * 3 + jo] = acc;
            }
        }
    }
}

extern "C" void kernel_launch(void* const* d_in, const int* in_sizes, int n_in,
                              void* d_out, int out_size) {
    const float* X     = (const float*)d_in[0];
    const float* Winit = (const float*)d_in[1];
    const float* binit = (const float*)d_in[2];
    const float* Wf1   = (const float*)d_in[3];
    const float* bf1   = (const float*)d_in[4];
    const float* Wf2   = (const float*)d_in[5];
    const float* bf2   = (const float*)d_in[6];
    const float* Wo1   = (const float*)d_in[7];
    const float* bo1   = (const float*)d_in[8];
    const float* Wo2   = (const float*)d_in[9];
    const float* bo2   = (const float*)d_in[10];
    float* out = (float*)d_out;

    // 410 CTAs x 128 thr: 2 pairs/CTA x 5 batches = 4100 slots >= 4096 (tail guarded)
    cde_kernel<<<NCTA, 128>>>(X, Winit, binit, Wf1, bf1, Wf2, bf2,
                              Wo1, bo1, Wo2, bo2, out);
}